// round 13
// baseline (speedup 1.0000x reference)
#include <cuda_runtime.h>
#include <cuda_fp16.h>

#define BB 2
#define CC 64
#define HH 192
#define WW 192
#define HWX (HH*WW)
#define KK 7

// q scratch fp32 quad layout; k scratch fp16 quad layout (half4 per uint2)
__device__ float4 d_q4[BB*16*HWX];
__device__ uint2  d_kh[BB*16*HWX];

__device__ __forceinline__ void ffma2(unsigned long long &acc,
                                      unsigned long long a,
                                      unsigned long long b) {
    asm("fma.rn.f32x2 %0, %1, %2, %0;" : "+l"(acc) : "l"(a), "l"(b));
}
__device__ __forceinline__ float f2lo(unsigned long long v) {
    return __uint_as_float((unsigned)(v & 0xffffffffu));
}
__device__ __forceinline__ float f2hi(unsigned long long v) {
    return __uint_as_float((unsigned)(v >> 32));
}
__device__ __forceinline__ int iclamp(int v, int hi) {
    return v < 0 ? 0 : (v > hi ? hi : v);
}

// ---------------------------------------------------------------------------
// Kernel 1: LN + [128x65] matvec, register-blocked, f32x2 FMA.
// In-block weight transpose (no k0): raw convw staged into zsh area, then
// smem->smem transpose (both directions conflict-free: stride 65 = odd).
// Parallel single-pass LN stats (all 256 threads).
// ---------------------------------------------------------------------------
#define K1_PIX 64
#define K1_NT 256
#define WSTRIDE 132
#define K1_SMEM (65*K1_PIX*8 + 65*WSTRIDE*4)

__global__ void __launch_bounds__(K1_NT)
mspn_k1(const float* __restrict__ g, const float* __restrict__ cd,
        const float* __restrict__ mask, const float* __restrict__ lnw,
        const float* __restrict__ lnb, const float* __restrict__ convw,
        const float* __restrict__ convb)
{
    extern __shared__ __align__(16) char dsm[];
    float2* zsh = (float2*)dsm;                       // [65][64]
    float*  wraw = (float*)dsm;                       // overlay (used pre-g)
    float*  wsh = (float*)(dsm + 65*K1_PIX*8);        // [65][WSTRIDE]
    __shared__ float mu_sh[K1_PIX], ri_sh[K1_PIX], mk_sh[K1_PIX];
    __shared__ float bsh[128];
    __shared__ float2 part[4][K1_PIX];

    const int t = threadIdx.x;
    const int p0 = blockIdx.x * K1_PIX;
    const int b = p0 / HWX;
    const int hw0 = p0 - b*HWX;

    // phase A: raw weights into zsh-area (coalesced both sides)
    for (int i = t; i < 128*65; i += K1_NT) wraw[i] = convw[i];
    if (t >= 128 && t < 256) bsh[t-128] = convb[t-128];
    __syncthreads();

    // transpose into wsh[c][oc]; read stride 65 words (odd -> conflict-free)
    for (int i = t; i < 65*128; i += K1_NT) {
        int c = i >> 7, oc = i & 127;
        wsh[c*WSTRIDE + oc] = wraw[oc*65 + c];
    }
    __syncthreads();

    // phase B: stage g over the raw-weight area
    for (int i = t; i < 64*K1_PIX; i += K1_NT) {
        int c = i >> 6, px = i & 63;
        zsh[c*K1_PIX + px].x = g[(b*CC + c)*HWX + hw0 + px];
    }
    if (t < K1_PIX) {
        float cv = cd[p0 + t];
        zsh[64*K1_PIX + t] = make_float2(cv, cv);
        mk_sh[t] = mask[p0 + t];
    }
    __syncthreads();

    // parallel LN stats: thread (px, qd) sums 16 channels
    {
        const int px = t & 63, qd = t >> 6;
        float s = 0.f, s2 = 0.f;
        #pragma unroll
        for (int i = 0; i < 16; i++) {
            float v = zsh[(qd*16 + i)*K1_PIX + px].x;
            s += v; s2 += v*v;
        }
        part[qd][px] = make_float2(s, s2);
    }
    __syncthreads();
    if (t < K1_PIX) {
        float2 a0 = part[0][t], a1 = part[1][t], a2 = part[2][t], a3 = part[3][t];
        float S  = a0.x + a1.x + a2.x + a3.x;
        float S2 = a0.y + a1.y + a2.y + a3.y;
        float mu = S * (1.f/64.f);
        float var = S2 * (1.f/64.f) - mu*mu;
        mu_sh[t] = mu;
        ri_sh[t] = rsqrtf(var + 1e-6f);
    }
    __syncthreads();

    for (int i = t; i < 64*K1_PIX; i += K1_NT) {
        int c = i >> 6, px = i & 63;
        float v = (zsh[c*K1_PIX + px].x - mu_sh[px]) * ri_sh[px] * lnw[c] + lnb[c];
        zsh[c*K1_PIX + px] = make_float2(v, v);
    }
    __syncthreads();

    const int lane = t & 31, wid = t >> 5;
    const int oc0 = wid * 16;

    unsigned long long acc[16];
    #pragma unroll
    for (int i = 0; i < 16; i++) acc[i] = 0ULL;

    #pragma unroll 13
    for (int c = 0; c < 65; c++) {
        unsigned long long z0 = *(const unsigned long long*)&zsh[c*K1_PIX + lane];
        unsigned long long z1 = *(const unsigned long long*)&zsh[c*K1_PIX + lane + 32];
        const float* wr = &wsh[c*WSTRIDE + oc0];
        ulonglong2 wa = *(const ulonglong2*)(wr);
        ulonglong2 wb = *(const ulonglong2*)(wr + 4);
        ulonglong2 wc = *(const ulonglong2*)(wr + 8);
        ulonglong2 wd = *(const ulonglong2*)(wr + 12);
        ffma2(acc[0], z0, wa.x); ffma2(acc[1], z0, wa.y);
        ffma2(acc[2], z0, wb.x); ffma2(acc[3], z0, wb.y);
        ffma2(acc[4], z0, wc.x); ffma2(acc[5], z0, wc.y);
        ffma2(acc[6], z0, wd.x); ffma2(acc[7], z0, wd.y);
        ffma2(acc[8],  z1, wa.x); ffma2(acc[9],  z1, wa.y);
        ffma2(acc[10], z1, wb.x); ffma2(acc[11], z1, wb.y);
        ffma2(acc[12], z1, wc.x); ffma2(acc[13], z1, wc.y);
        ffma2(acc[14], z1, wd.x); ffma2(acc[15], z1, wd.y);
    }

    const bool isk = (oc0 >= 64);
    const int cq0 = (isk ? oc0 - 64 : oc0) >> 2;
    float bias[16];
    #pragma unroll
    for (int i = 0; i < 16; i++) bias[i] = bsh[oc0 + i];

    #pragma unroll
    for (int px = 0; px < 2; px++) {
        const int pl = lane + px*32;
        const int pix = hw0 + pl;
        const float m = mk_sh[pl];
        float vals[16];
        #pragma unroll
        for (int j = 0; j < 8; j++) {
            unsigned long long a = acc[px*8 + j];
            vals[2*j]   = f2lo(a) + bias[2*j];
            vals[2*j+1] = f2hi(a) + bias[2*j+1];
        }
        if (isk) {
            #pragma unroll
            for (int q = 0; q < 4; q++) {
                __half2 h01 = __floats2half2_rn(vals[4*q]*m,   vals[4*q+1]*m);
                __half2 h23 = __floats2half2_rn(vals[4*q+2]*m, vals[4*q+3]*m);
                uint2 o;
                o.x = *(unsigned*)&h01;
                o.y = *(unsigned*)&h23;
                d_kh[(b*16 + cq0 + q)*HWX + pix] = o;
            }
        } else {
            #pragma unroll
            for (int q = 0; q < 4; q++) {
                float4 o = make_float4(vals[4*q], vals[4*q+1], vals[4*q+2], vals[4*q+3]);
                d_q4[(b*16 + cq0 + q)*HWX + pix] = o;
            }
        }
    }
}

// ---------------------------------------------------------------------------
// Kernel 2: 7x7 clamped-window attention; fp16 k, fp32 q/accum.
// Register-prefetch double-buffered pipeline. (unchanged from R12 winner)
// ---------------------------------------------------------------------------
#define TX 32
#define TY 8
#define K2_NT 256
#define HR 14
#define HC 38
#define HSZ (HR*HC)

__global__ void __launch_bounds__(K2_NT, 2)
mspn_k2(const float* __restrict__ cd, const float* __restrict__ sd,
        const float* __restrict__ mask, const float* __restrict__ rpb,
        float* __restrict__ out)
{
    __shared__ uint2 ksh[2][4][HSZ];   // [buf][quad][pos] fp16 half4
    __shared__ float cdsh[HSZ];
    __shared__ float msh[HSZ];
    __shared__ float rpbsh[169];

    const int t = threadIdx.x;
    const int b  = blockIdx.z;
    const int h0 = blockIdx.y * TY;
    const int w0 = blockIdx.x * TX;
    const int r_off = h0 - 3, c_off = w0 - 3;

    // static staging slots + precomputed clamped global offsets
    const int i0 = t, i1 = t + K2_NT, i2 = t + 2*K2_NT;
    const bool has2 = (i2 < HSZ);
    int g0, g1, g2 = 0;
    { int rr = i0/HC, cc = i0 - rr*HC;
      g0 = iclamp(r_off + rr, HH-1)*WW + iclamp(c_off + cc, WW-1); }
    { int rr = i1/HC, cc = i1 - rr*HC;
      g1 = iclamp(r_off + rr, HH-1)*WW + iclamp(c_off + cc, WW-1); }
    if (has2) { int rr = i2/HC, cc = i2 - rr*HC;
      g2 = iclamp(r_off + rr, HH-1)*WW + iclamp(c_off + cc, WW-1); }

    const uint2* kgl = &d_kh[b*16*HWX];

    // prefetch round 0 k into registers
    uint2 pf[4][3];
    #pragma unroll
    for (int s = 0; s < 4; s++) {
        const uint2* src = kgl + s*HWX;
        pf[s][0] = src[g0];
        pf[s][1] = src[g1];
        if (has2) pf[s][2] = src[g2];
    }

    // cd/mask halo staging with the same offsets
    {
        const float* cdb = cd + b*HWX;
        const float* mb  = mask + b*HWX;
        cdsh[i0] = cdb[g0]; msh[i0] = mb[g0];
        cdsh[i1] = cdb[g1]; msh[i1] = mb[g1];
        if (has2) { cdsh[i2] = cdb[g2]; msh[i2] = mb[g2]; }
    }
    if (t < 169) rpbsh[t] = rpb[t];

    const int lw = t & 31, lh = t >> 5;
    const int h = h0 + lh, w = w0 + lw;
    int rs = h - 3; if (rs < 0) rs = 0; if (rs > HH-KK) rs = HH-KK;
    int cs = w - 3; if (cs < 0) cs = 0; if (cs > WW-KK) cs = WW-KK;
    const int ri0 = rs - r_off;
    const int ci0 = cs - c_off;

    float attn[49];
    #pragma unroll
    for (int i = 0; i < 49; i++) attn[i] = 0.f;

    const int qpix = h*WW + w;
    const float4* qb = &d_q4[b*16*HWX + qpix];

    for (int rd = 0; rd < 4; rd++) {
        __syncthreads();   // buf[rd&1] reads from round rd-2 complete
        {
            uint2 (*buf)[HSZ] = ksh[rd & 1];
            #pragma unroll
            for (int s = 0; s < 4; s++) {
                buf[s][i0] = pf[s][0];
                buf[s][i1] = pf[s][1];
                if (has2) buf[s][i2] = pf[s][2];
            }
        }
        __syncthreads();   // tile visible

        if (rd < 3) {       // prefetch next round (latency hides under compute)
            #pragma unroll
            for (int s = 0; s < 4; s++) {
                const uint2* src = kgl + ((rd+1)*4 + s)*HWX;
                pf[s][0] = src[g0];
                pf[s][1] = src[g1];
                if (has2) pf[s][2] = src[g2];
            }
        }

        float4 q[4];
        #pragma unroll
        for (int s = 0; s < 4; s++) q[s] = qb[(4*rd + s)*HWX];

        #pragma unroll
        for (int s = 0; s < 4; s++) {
            const float4 qq = q[s];
            const uint2* kb = &ksh[rd & 1][s][ri0*HC + ci0];
            #pragma unroll
            for (int i = 0; i < KK; i++) {
                #pragma unroll
                for (int j = 0; j < KK; j++) {
                    uint2 kk = kb[i*HC + j];
                    float2 f01 = __half22float2(*reinterpret_cast<__half2*>(&kk.x));
                    float2 f23 = __half22float2(*reinterpret_cast<__half2*>(&kk.y));
                    attn[i*KK+j] += qq.x*f01.x + qq.y*f01.y + qq.z*f23.x + qq.w*f23.y;
                }
            }
        }
    }

    // bias + softmax
    const int pbr = 6 - (h - rs);
    const int pbc = 6 - (w - cs);
    float mx = -1e30f;
    #pragma unroll
    for (int i = 0; i < KK; i++) {
        #pragma unroll
        for (int j = 0; j < KK; j++) {
            float a = attn[i*KK+j] + rpbsh[(pbr+i)*13 + pbc + j];
            attn[i*KK+j] = a;
            mx = fmaxf(mx, a);
        }
    }
    float ssum = 0.f;
    #pragma unroll
    for (int i = 0; i < 49; i++) {
        float e = __expf(attn[i] - mx);
        attn[i] = e;
        ssum += e;
    }
    const float inv = 1.f / ssum;

    float cdo = 0.f, mo = 0.f;
    #pragma unroll
    for (int i = 0; i < KK; i++) {
        #pragma unroll
        for (int j = 0; j < KK; j++) {
            float a = attn[i*KK+j];
            cdo += a * cdsh[(ri0+i)*HC + ci0 + j];
            mo  += a * msh[(ri0+i)*HC + ci0 + j];
        }
    }
    cdo *= inv; mo *= inv;

    const int p = b*HWX + h*WW + w;
    const float m = mask[p], cdv = cd[p], sdv = sd[p];
    cdo = cdo*m + cdv*(1.f - m);
    if (sdv > 0.f) { cdo = sdv; mo = m; }
    out[p] = cdo;
    out[BB*HWX + p] = mo;
}

// ---------------------------------------------------------------------------
extern "C" void kernel_launch(void* const* d_in, const int* in_sizes, int n_in,
                              void* d_out, int out_size)
{
    const float* g     = (const float*)d_in[0];
    const float* cd    = (const float*)d_in[1];
    const float* sd    = (const float*)d_in[2];
    const float* mask  = (const float*)d_in[3];
    const float* lnw   = (const float*)d_in[4];
    const float* lnb   = (const float*)d_in[5];
    const float* convw = (const float*)d_in[6];
    const float* convb = (const float*)d_in[7];
    const float* rpb   = (const float*)d_in[8];
    float* out = (float*)d_out;

    cudaFuncSetAttribute(mspn_k1, cudaFuncAttributeMaxDynamicSharedMemorySize, K1_SMEM);
    mspn_k1<<<(BB*HWX)/K1_PIX, K1_NT, K1_SMEM>>>(g, cd, mask, lnw, lnb, convw, convb);

    dim3 grid2(WW/TX, HH/TY, BB);
    mspn_k2<<<grid2, K2_NT>>>(cd, sd, mask, rpb, out);
}

// round 17
// speedup vs baseline: 1.0836x; 1.0836x over previous
#include <cuda_runtime.h>
#include <cuda_fp16.h>

#define BB 2
#define CC 64
#define HH 192
#define WW 192
#define HWX (HH*WW)
#define KK 7

// q scratch fp32 quad layout; k scratch fp16 quad layout (half4 per uint2)
__device__ float4 d_q4[BB*16*HWX];
__device__ uint2  d_kh[BB*16*HWX];

__device__ __forceinline__ void ffma2(unsigned long long &acc,
                                      unsigned long long a,
                                      unsigned long long b) {
    asm("fma.rn.f32x2 %0, %1, %2, %0;" : "+l"(acc) : "l"(a), "l"(b));
}
__device__ __forceinline__ float f2lo(unsigned long long v) {
    return __uint_as_float((unsigned)(v & 0xffffffffu));
}
__device__ __forceinline__ float f2hi(unsigned long long v) {
    return __uint_as_float((unsigned)(v >> 32));
}
__device__ __forceinline__ int iclamp(int v, int hi) {
    return v < 0 ? 0 : (v > hi ? hi : v);
}

// ---------------------------------------------------------------------------
// Kernel 1: LN + [128x65] matvec, register-blocked, f32x2 FMA.
// 4 pixel-phases per block: weights staged+transposed ONCE, then 4 x 64 px
// (stage g -> parallel LN -> GEMM -> epilogue). Amortizes the 33KB weight
// prologue 4x; grid 288 blocks.
// ---------------------------------------------------------------------------
#define K1_PIX 64
#define K1_NT 256
#define K1_PH 4
#define WSTRIDE 132
#define K1_SMEM (65*K1_PIX*8 + 65*WSTRIDE*4)

__global__ void __launch_bounds__(K1_NT)
mspn_k1(const float* __restrict__ g, const float* __restrict__ cd,
        const float* __restrict__ mask, const float* __restrict__ lnw,
        const float* __restrict__ lnb, const float* __restrict__ convw,
        const float* __restrict__ convb)
{
    extern __shared__ __align__(16) char dsm[];
    float2* zsh = (float2*)dsm;                       // [65][64]
    float*  wraw = (float*)dsm;                       // overlay (pre-g only)
    float*  wsh = (float*)(dsm + 65*K1_PIX*8);        // [65][WSTRIDE]
    __shared__ float mu_sh[K1_PIX], ri_sh[K1_PIX], mk_sh[K1_PIX];
    __shared__ float bsh[128];
    __shared__ float2 part[4][K1_PIX];

    const int t = threadIdx.x;
    const int lane = t & 31, wid = t >> 5;
    const int oc0 = wid * 16;
    const int blk0 = blockIdx.x * (K1_PIX * K1_PH);

    // ---- once per block: weights ----
    for (int i = t; i < 128*65; i += K1_NT) wraw[i] = convw[i];
    if (t >= 128 && t < 256) bsh[t-128] = convb[t-128];
    __syncthreads();
    for (int i = t; i < 65*128; i += K1_NT) {
        int c = i >> 7, oc = i & 127;
        wsh[c*WSTRIDE + oc] = wraw[oc*65 + c];   // stride 65 = odd: no conflicts
    }

    const bool isk = (oc0 >= 64);
    const int cq0 = (isk ? oc0 - 64 : oc0) >> 2;
    float bias[16];
    #pragma unroll
    for (int i = 0; i < 16; i++) bias[i] = convb[oc0 + i];

    for (int ph = 0; ph < K1_PH; ph++) {
        const int p0 = blk0 + ph * K1_PIX;
        const int b = p0 / HWX;
        const int hw0 = p0 - b*HWX;

        __syncthreads();   // prior phase GEMM reads of zsh complete (and transpose)
        for (int i = t; i < 64*K1_PIX; i += K1_NT) {
            int c = i >> 6, px = i & 63;
            zsh[c*K1_PIX + px].x = g[(b*CC + c)*HWX + hw0 + px];
        }
        if (t < K1_PIX) {
            float cv = cd[p0 + t];
            zsh[64*K1_PIX + t] = make_float2(cv, cv);
            mk_sh[t] = mask[p0 + t];
        }
        __syncthreads();

        // parallel LN stats: thread (px, qd) sums 16 channels
        {
            const int px = t & 63, qd = t >> 6;
            float s = 0.f, s2 = 0.f;
            #pragma unroll
            for (int i = 0; i < 16; i++) {
                float v = zsh[(qd*16 + i)*K1_PIX + px].x;
                s += v; s2 += v*v;
            }
            part[qd][px] = make_float2(s, s2);
        }
        __syncthreads();
        if (t < K1_PIX) {
            float2 a0 = part[0][t], a1 = part[1][t], a2 = part[2][t], a3 = part[3][t];
            float S  = a0.x + a1.x + a2.x + a3.x;
            float S2 = a0.y + a1.y + a2.y + a3.y;
            float mu = S * (1.f/64.f);
            float var = S2 * (1.f/64.f) - mu*mu;
            mu_sh[t] = mu;
            ri_sh[t] = rsqrtf(var + 1e-6f);
        }
        __syncthreads();

        for (int i = t; i < 64*K1_PIX; i += K1_NT) {
            int c = i >> 6, px = i & 63;
            float v = (zsh[c*K1_PIX + px].x - mu_sh[px]) * ri_sh[px] * lnw[c] + lnb[c];
            zsh[c*K1_PIX + px] = make_float2(v, v);
        }
        __syncthreads();

        unsigned long long acc[16];
        #pragma unroll
        for (int i = 0; i < 16; i++) acc[i] = 0ULL;

        #pragma unroll 13
        for (int c = 0; c < 65; c++) {
            unsigned long long z0 = *(const unsigned long long*)&zsh[c*K1_PIX + lane];
            unsigned long long z1 = *(const unsigned long long*)&zsh[c*K1_PIX + lane + 32];
            const float* wr = &wsh[c*WSTRIDE + oc0];
            ulonglong2 wa = *(const ulonglong2*)(wr);
            ulonglong2 wb = *(const ulonglong2*)(wr + 4);
            ulonglong2 wc = *(const ulonglong2*)(wr + 8);
            ulonglong2 wd = *(const ulonglong2*)(wr + 12);
            ffma2(acc[0], z0, wa.x); ffma2(acc[1], z0, wa.y);
            ffma2(acc[2], z0, wb.x); ffma2(acc[3], z0, wb.y);
            ffma2(acc[4], z0, wc.x); ffma2(acc[5], z0, wc.y);
            ffma2(acc[6], z0, wd.x); ffma2(acc[7], z0, wd.y);
            ffma2(acc[8],  z1, wa.x); ffma2(acc[9],  z1, wa.y);
            ffma2(acc[10], z1, wb.x); ffma2(acc[11], z1, wb.y);
            ffma2(acc[12], z1, wc.x); ffma2(acc[13], z1, wc.y);
            ffma2(acc[14], z1, wd.x); ffma2(acc[15], z1, wd.y);
        }

        #pragma unroll
        for (int px = 0; px < 2; px++) {
            const int pl = lane + px*32;
            const int pix = hw0 + pl;
            const float m = mk_sh[pl];
            float vals[16];
            #pragma unroll
            for (int j = 0; j < 8; j++) {
                unsigned long long a = acc[px*8 + j];
                vals[2*j]   = f2lo(a) + bias[2*j];
                vals[2*j+1] = f2hi(a) + bias[2*j+1];
            }
            if (isk) {
                #pragma unroll
                for (int q = 0; q < 4; q++) {
                    __half2 h01 = __floats2half2_rn(vals[4*q]*m,   vals[4*q+1]*m);
                    __half2 h23 = __floats2half2_rn(vals[4*q+2]*m, vals[4*q+3]*m);
                    uint2 o;
                    o.x = *(unsigned*)&h01;
                    o.y = *(unsigned*)&h23;
                    d_kh[(b*16 + cq0 + q)*HWX + pix] = o;
                }
            } else {
                #pragma unroll
                for (int q = 0; q < 4; q++) {
                    float4 o = make_float4(vals[4*q], vals[4*q+1], vals[4*q+2], vals[4*q+3]);
                    d_q4[(b*16 + cq0 + q)*HWX + pix] = o;
                }
            }
        }
    }
}

// ---------------------------------------------------------------------------
// Kernel 2: 7x7 clamped-window attention; fp16 k, fp32 q/accum.
// Register-prefetch double-buffered pipeline. (unchanged R12/R13 winner)
// ---------------------------------------------------------------------------
#define TX 32
#define TY 8
#define K2_NT 256
#define HR 14
#define HC 38
#define HSZ (HR*HC)

__global__ void __launch_bounds__(K2_NT, 2)
mspn_k2(const float* __restrict__ cd, const float* __restrict__ sd,
        const float* __restrict__ mask, const float* __restrict__ rpb,
        float* __restrict__ out)
{
    __shared__ uint2 ksh[2][4][HSZ];   // [buf][quad][pos] fp16 half4
    __shared__ float cdsh[HSZ];
    __shared__ float msh[HSZ];
    __shared__ float rpbsh[169];

    const int t = threadIdx.x;
    const int b  = blockIdx.z;
    const int h0 = blockIdx.y * TY;
    const int w0 = blockIdx.x * TX;
    const int r_off = h0 - 3, c_off = w0 - 3;

    const int i0 = t, i1 = t + K2_NT, i2 = t + 2*K2_NT;
    const bool has2 = (i2 < HSZ);
    int g0, g1, g2 = 0;
    { int rr = i0/HC, cc = i0 - rr*HC;
      g0 = iclamp(r_off + rr, HH-1)*WW + iclamp(c_off + cc, WW-1); }
    { int rr = i1/HC, cc = i1 - rr*HC;
      g1 = iclamp(r_off + rr, HH-1)*WW + iclamp(c_off + cc, WW-1); }
    if (has2) { int rr = i2/HC, cc = i2 - rr*HC;
      g2 = iclamp(r_off + rr, HH-1)*WW + iclamp(c_off + cc, WW-1); }

    const uint2* kgl = &d_kh[b*16*HWX];

    uint2 pf[4][3];
    #pragma unroll
    for (int s = 0; s < 4; s++) {
        const uint2* src = kgl + s*HWX;
        pf[s][0] = src[g0];
        pf[s][1] = src[g1];
        if (has2) pf[s][2] = src[g2];
    }

    {
        const float* cdb = cd + b*HWX;
        const float* mb  = mask + b*HWX;
        cdsh[i0] = cdb[g0]; msh[i0] = mb[g0];
        cdsh[i1] = cdb[g1]; msh[i1] = mb[g1];
        if (has2) { cdsh[i2] = cdb[g2]; msh[i2] = mb[g2]; }
    }
    if (t < 169) rpbsh[t] = rpb[t];

    const int lw = t & 31, lh = t >> 5;
    const int h = h0 + lh, w = w0 + lw;
    int rs = h - 3; if (rs < 0) rs = 0; if (rs > HH-KK) rs = HH-KK;
    int cs = w - 3; if (cs < 0) cs = 0; if (cs > WW-KK) cs = WW-KK;
    const int ri0 = rs - r_off;
    const int ci0 = cs - c_off;

    float attn[49];
    #pragma unroll
    for (int i = 0; i < 49; i++) attn[i] = 0.f;

    const int qpix = h*WW + w;
    const float4* qb = &d_q4[b*16*HWX + qpix];

    for (int rd = 0; rd < 4; rd++) {
        __syncthreads();
        {
            uint2 (*buf)[HSZ] = ksh[rd & 1];
            #pragma unroll
            for (int s = 0; s < 4; s++) {
                buf[s][i0] = pf[s][0];
                buf[s][i1] = pf[s][1];
                if (has2) buf[s][i2] = pf[s][2];
            }
        }
        __syncthreads();

        if (rd < 3) {
            #pragma unroll
            for (int s = 0; s < 4; s++) {
                const uint2* src = kgl + ((rd+1)*4 + s)*HWX;
                pf[s][0] = src[g0];
                pf[s][1] = src[g1];
                if (has2) pf[s][2] = src[g2];
            }
        }

        float4 q[4];
        #pragma unroll
        for (int s = 0; s < 4; s++) q[s] = qb[(4*rd + s)*HWX];

        #pragma unroll
        for (int s = 0; s < 4; s++) {
            const float4 qq = q[s];
            const uint2* kb = &ksh[rd & 1][s][ri0*HC + ci0];
            #pragma unroll
            for (int i = 0; i < KK; i++) {
                #pragma unroll
                for (int j = 0; j < KK; j++) {
                    uint2 kk = kb[i*HC + j];
                    float2 f01 = __half22float2(*reinterpret_cast<__half2*>(&kk.x));
                    float2 f23 = __half22float2(*reinterpret_cast<__half2*>(&kk.y));
                    attn[i*KK+j] += qq.x*f01.x + qq.y*f01.y + qq.z*f23.x + qq.w*f23.y;
                }
            }
        }
    }

    const int pbr = 6 - (h - rs);
    const int pbc = 6 - (w - cs);
    float mx = -1e30f;
    #pragma unroll
    for (int i = 0; i < KK; i++) {
        #pragma unroll
        for (int j = 0; j < KK; j++) {
            float a = attn[i*KK+j] + rpbsh[(pbr+i)*13 + pbc + j];
            attn[i*KK+j] = a;
            mx = fmaxf(mx, a);
        }
    }
    float ssum = 0.f;
    #pragma unroll
    for (int i = 0; i < 49; i++) {
        float e = __expf(attn[i] - mx);
        attn[i] = e;
        ssum += e;
    }
    const float inv = 1.f / ssum;

    float cdo = 0.f, mo = 0.f;
    #pragma unroll
    for (int i = 0; i < KK; i++) {
        #pragma unroll
        for (int j = 0; j < KK; j++) {
            float a = attn[i*KK+j];
            cdo += a * cdsh[(ri0+i)*HC + ci0 + j];
            mo  += a * msh[(ri0+i)*HC + ci0 + j];
        }
    }
    cdo *= inv; mo *= inv;

    const int p = b*HWX + h*WW + w;
    const float m = mask[p], cdv = cd[p], sdv = sd[p];
    cdo = cdo*m + cdv*(1.f - m);
    if (sdv > 0.f) { cdo = sdv; mo = m; }
    out[p] = cdo;
    out[BB*HWX + p] = mo;
}

// ---------------------------------------------------------------------------
extern "C" void kernel_launch(void* const* d_in, const int* in_sizes, int n_in,
                              void* d_out, int out_size)
{
    const float* g     = (const float*)d_in[0];
    const float* cd    = (const float*)d_in[1];
    const float* sd    = (const float*)d_in[2];
    const float* mask  = (const float*)d_in[3];
    const float* lnw   = (const float*)d_in[4];
    const float* lnb   = (const float*)d_in[5];
    const float* convw = (const float*)d_in[6];
    const float* convb = (const float*)d_in[7];
    const float* rpb   = (const float*)d_in[8];
    float* out = (float*)d_out;

    cudaFuncSetAttribute(mspn_k1, cudaFuncAttributeMaxDynamicSharedMemorySize, K1_SMEM);
    mspn_k1<<<(BB*HWX)/(K1_PIX*K1_PH), K1_NT, K1_SMEM>>>(g, cd, mask, lnw, lnb, convw, convb);

    dim3 grid2(WW/TX, HH/TY, BB);
    mspn_k2<<<grid2, K2_NT>>>(cd, sd, mask, rpb, out);
}